// round 10
// baseline (speedup 1.0000x reference)
#include <cuda_runtime.h>

#define HWc   4096
#define NPIX  16384   // B*H*W
#define Cc    256
#define CPc   32
#define EPSc  1e-5f

__device__ float g_km[NPIX*CPc];
__device__ float g_qm[NPIX*CPc];
__device__ float g_xm[NPIX*CPc];
__device__ float g_pre[NPIX*CPc];
__device__ float g_part[64*1056];
__device__ float g_ab[2*Cc];
__device__ unsigned int g_cnt;   // zero-init; self-resets each call

// ---------------------------------------------------------------------------
// K1 (merged): km/qm/xm = conv1x1(x, {wk,wq,wx}) in ONE pass over x.
// Block = 32-pixel tile x ALL 96 output channels; x read once (was 3x).
// block 256: tx = pixel (32), ty = out-group of 12 (8 groups x 12 = 96 outs).
// Inner loop: 1 xs broadcast + 3 LDS.128 + 12 FMA per cc (24 FMA per xs-LDS).
// ---------------------------------------------------------------------------
__global__ void k1_kqx(const float* __restrict__ x, const float* __restrict__ vessel,
                       const float* __restrict__ wk, const float* __restrict__ bk,
                       const float* __restrict__ wq, const float* __restrict__ bq,
                       const float* __restrict__ wx, const float* __restrict__ bx)
{
    __shared__ __align__(16) float xs[32][32];     // [cc][px]
    __shared__ __align__(16) float ws[32][96];     // [cc][out 0..95 = k|q|x]
    __shared__ float bs[96];
    __shared__ float vs[32];
    int t  = threadIdx.x;
    int tx = t & 31;          // pixel within tile
    int ty = t >> 5;          // output group of 12 (8 groups -> 96 outs)

    int p0 = blockIdx.x * 32;
    const float* xb = x + (size_t)(p0 >> 12) * (Cc*HWc) + (p0 & (HWc-1));

    if (t < 96) bs[t] = (t < 32) ? bk[t] : (t < 64) ? bq[t-32] : bx[t-64];
    if (t < 32) vs[t] = vessel[p0 + t];

    float acc[12];
#pragma unroll
    for (int i = 0; i < 12; ++i) acc[i] = 0.f;

    for (int c0 = 0; c0 < Cc; c0 += 32) {
        // stage x tile: 32 ch x 32 px
#pragma unroll
        for (int i = 0; i < 4; ++i) {
            int idx = i*256 + t;
            int cc = idx >> 5, px = idx & 31;
            xs[cc][px] = xb[(size_t)(c0+cc)*HWc + px];
        }
        // stage weights: 32 ch x 96 outs
#pragma unroll
        for (int i = 0; i < 12; ++i) {
            int e = i*256 + t;
            int cc = e & 31, o = e >> 5;
            const float* W = (o < 32) ? wk : (o < 64) ? wq : wx;
            int r = o & 31;
            ws[cc][o] = W[r*Cc + c0 + cc];
        }
        __syncthreads();
#pragma unroll
        for (int cc = 0; cc < 32; ++cc) {
            float xv = xs[cc][tx];
            const float4* wr = (const float4*)&ws[cc][ty*12];
            float4 w0 = wr[0], w1 = wr[1], w2 = wr[2];
            acc[0]  += w0.x*xv; acc[1]  += w0.y*xv; acc[2]  += w0.z*xv; acc[3]  += w0.w*xv;
            acc[4]  += w1.x*xv; acc[5]  += w1.y*xv; acc[6]  += w1.z*xv; acc[7]  += w1.w*xv;
            acc[8]  += w2.x*xv; acc[9]  += w2.y*xv; acc[10] += w2.z*xv; acc[11] += w2.w*xv;
        }
        __syncthreads();
    }

    int p = p0 + tx;
    float vscale = vs[tx];
#pragma unroll
    for (int j = 0; j < 12; ++j) {
        int o = ty*12 + j;
        int m = o >> 5, r = o & 31;
        float v = acc[j] + bs[o];
        if (m == 0) { g_km[(size_t)p*CPc + r] = v * vscale; }
        else if (m == 1) { g_qm[(size_t)p*CPc + r] = v; }
        else { g_xm[(size_t)p*CPc + r] = v; }
    }
}

// ---------------------------------------------------------------------------
// K2: multi-scale local attention, fused across nested windows (3<5<7<9).
// R9 version (frozen): warp = 4 px, 8 lanes/px, 4 ch/lane; 1024 blocks x 128;
// no max-shift; exp + nested z sums fused into pass 1; pass 3 uses
// pre-combined coefficients selected at compile time.
// ---------------------------------------------------------------------------
__global__ void k2_attn()
{
    __shared__ float sc[4][81*4];   // per-warp exp buffer: [j][pixel-in-warp]
    int t    = threadIdx.x;
    int lane = t & 31, warp = t >> 5;
    int pxg  = lane >> 3;           // pixel in warp (0..3)
    int cg   = lane & 7;            // channel group (4 ch each)
    int p  = blockIdx.x * 16 + warp * 4 + pxg;
    int hw = p & (HWc-1);
    int h  = hw >> 6, w = hw & 63;

    const float* kmrow = g_km + (size_t)p*CPc + cg*4;
    const float* xmrow = g_xm + (size_t)p*CPc + cg*4;
    float4 q = *(const float4*)(g_qm + (size_t)p*CPc + cg*4);
    float* scp = sc[warp];

    // pass 1: scores -> e = exp(s), nested z sums in registers
    float z1=0.f, z2=0.f, z3=0.f, z4=0.f;
#pragma unroll
    for (int dy = -4; dy <= 4; ++dy) {
#pragma unroll
        for (int dx = -4; dx <= 4; ++dx) {
            int j = (dy+4)*9 + (dx+4);
            bool ok = ((unsigned)(h+dy) < 64u) && ((unsigned)(w+dx) < 64u);
            float4 km4 = make_float4(0.f,0.f,0.f,0.f);
            if (ok) km4 = *(const float4*)(kmrow + (dy*64+dx)*CPc);
            float s = km4.x*q.x + km4.y*q.y + km4.z*q.z + km4.w*q.w;
            s += __shfl_xor_sync(0xffffffffu, s, 1);
            s += __shfl_xor_sync(0xffffffffu, s, 2);
            s += __shfl_xor_sync(0xffffffffu, s, 4);
            float e = __expf(s);
            if (cg == 0) scp[j*4 + pxg] = e;
            const int ady = (dy < 0) ? -dy : dy;
            const int adx = (dx < 0) ? -dx : dx;
            const int a = (ady > adx) ? ady : adx;   // compile-time constant
            z4 += e;
            if (a <= 3) z3 += e;
            if (a <= 2) z2 += e;
            if (a <= 1) z1 += e;
        }
    }
    __syncwarp();

    float i4 = 1.0f/z4;
    float i3 = 1.0f/z3;
    float i2 = 1.0f/z2;
    float i1 = 1.0f/z1;
    float c4 = i4;
    float c3 = i4 + i3;
    float c2 = i4 + i3 + i2;
    float c1 = i4 + i3 + i2 + i1;

    // pass 3: weighted sweep, coefficient selected at compile time per offset
    float ax=0.f, ay=0.f, az=0.f, aw=0.f;
#pragma unroll
    for (int dy = -4; dy <= 4; ++dy) {
#pragma unroll
        for (int dx = -4; dx <= 4; ++dx) {
            int j = (dy+4)*9 + (dx+4);
            bool ok = ((unsigned)(h+dy) < 64u) && ((unsigned)(w+dx) < 64u);
            if (!ok) continue;   // OOB value == 0
            const int ady = (dy < 0) ? -dy : dy;
            const int adx = (dx < 0) ? -dx : dx;
            const int a = (ady > adx) ? ady : adx;   // compile-time constant
            float coef = (a <= 1) ? c1 : (a == 2) ? c2 : (a == 3) ? c3 : c4;
            float wj = scp[j*4 + pxg] * coef;
            float4 xm4 = *(const float4*)(xmrow + (dy*64+dx)*CPc);
            ax += wj*xm4.x; ay += wj*xm4.y; az += wj*xm4.z; aw += wj*xm4.w;
        }
    }
    *(float4*)(g_pre + (size_t)p*CPc + cg*4) = make_float4(ax, ay, az, aw);
}

// ---------------------------------------------------------------------------
// K3: fused BN-stats. Phase 1 (all 64 blocks): partial mean[32] + S[32][32]
// over a 256-pixel chunk. Phase 2 (last-arriving block, threadfence+counter):
// reduce partials, var_y = w^T S w - (w.mu)^2, fold into per-channel affine.
// ---------------------------------------------------------------------------
__global__ void k3_stats(const float* __restrict__ wf, const float* __restrict__ bf,
                         const float* __restrict__ gamma, const float* __restrict__ beta)
{
    __shared__ __align__(16) float ps[256*32];
    int t = threadIdx.x;
    size_t base = (size_t)blockIdx.x * 256 * 32;
#pragma unroll
    for (int i = 0; i < 32; ++i)
        ps[i*256 + t] = g_pre[base + i*256 + t];
    __syncthreads();

    int i  = t >> 3;
    int j4 = (t & 7) * 4;
    float s0=0.f, s1=0.f, s2=0.f, s3=0.f;
    for (int p = 0; p < 256; ++p) {
        float a  = ps[p*32 + i];
        float4 b = *(const float4*)&ps[p*32 + j4];
        s0 += a*b.x; s1 += a*b.y; s2 += a*b.z; s3 += a*b.w;
    }
    float* part = g_part + blockIdx.x * 1056;
    part[32 + i*32 + j4 + 0] = s0;
    part[32 + i*32 + j4 + 1] = s1;
    part[32 + i*32 + j4 + 2] = s2;
    part[32 + i*32 + j4 + 3] = s3;
    if (t < 32) {
        float mm = 0.f;
        for (int p = 0; p < 256; ++p) mm += ps[p*32 + t];
        part[t] = mm;
    }
    __threadfence();
    __syncthreads();

    __shared__ unsigned int amLast;
    if (t == 0) amLast = atomicAdd(&g_cnt, 1u);
    __syncthreads();
    if (amLast != 63u) return;

    float* S = ps;   // reuse smem
    for (int e = t; e < 1056; e += 256) {
        float s = 0.f;
#pragma unroll
        for (int b = 0; b < 64; ++b) s += g_part[b*1056 + e];
        S[e] = s * (1.0f/16384.0f);
    }
    __syncthreads();

    {
        float wreg[32];
#pragma unroll
        for (int c = 0; c < 32; ++c) wreg[c] = wf[t*32 + c];
        float wmu = 0.f;
#pragma unroll
        for (int c = 0; c < 32; ++c) wmu += wreg[c] * S[c];
        float qf = 0.f;
        for (int c = 0; c < 32; ++c) {
            float tc = 0.f;
#pragma unroll
            for (int d = 0; d < 32; ++d) tc += S[32 + c*32 + d] * wreg[d];
            qf += wreg[c] * tc;
        }
        float var   = qf - wmu*wmu;
        float meanY = wmu + bf[t];
        float a = gamma[t] * rsqrtf(var + EPSc);
        g_ab[t]       = a;
        g_ab[256 + t] = beta[t] - a * meanY;
    }
    if (t == 0) g_cnt = 0u;   // reset for next graph replay
}

// ---------------------------------------------------------------------------
// K4: out = x + a[co]*(wf.pre) + bb[co]  (bb = a*bf + beta - a*meanY, folded)
// grid (128 px-tiles of 128, 4 co-groups of 64), block 128.  (R6 version)
// ---------------------------------------------------------------------------
__global__ void k4_final(const float* __restrict__ x, const float* __restrict__ wf,
                         const float* __restrict__ bf, float* __restrict__ out)
{
    __shared__ __align__(16) float ws[64*32];
    __shared__ float as[64], bbs[64];
    int t = threadIdx.x;
    int cog = blockIdx.y * 64;
#pragma unroll
    for (int i = 0; i < 16; ++i)
        ws[i*128 + t] = wf[cog*32 + i*128 + t];
    if (t < 64) {
        float a = g_ab[cog+t];
        as[t]  = a;
        bbs[t] = g_ab[256+cog+t] + a * bf[cog+t];
    }
    __syncthreads();

    int p = blockIdx.x * 128 + t;
    float pr[32];
#pragma unroll
    for (int c = 0; c < 32; c += 4) {
        float4 v = *(const float4*)(g_pre + (size_t)p*32 + c);
        pr[c]=v.x; pr[c+1]=v.y; pr[c+2]=v.z; pr[c+3]=v.w;
    }
    int b = p >> 12, hw = p & 4095;
    const float* xrow = x   + (size_t)b*(Cc*HWc) + hw;
    float*       orow = out + (size_t)b*(Cc*HWc) + hw;
    for (int co = 0; co < 64; ++co) {
        const float* wr = &ws[co*32];
        float y = 0.f;
#pragma unroll
        for (int c = 0; c < 32; ++c) y += wr[c] * pr[c];
        size_t off = (size_t)(cog + co) * HWc;
        orow[off] = xrow[off] + as[co]*y + bbs[co];
    }
}

// ---------------------------------------------------------------------------
extern "C" void kernel_launch(void* const* d_in, const int* in_sizes, int n_in,
                              void* d_out, int out_size)
{
    const float* x      = (const float*)d_in[0];
    const float* vessel = (const float*)d_in[1];
    const float* wk     = (const float*)d_in[2];
    const float* bk     = (const float*)d_in[3];
    const float* wq     = (const float*)d_in[4];
    const float* bq     = (const float*)d_in[5];
    const float* wx     = (const float*)d_in[6];
    const float* bx     = (const float*)d_in[7];
    const float* wf     = (const float*)d_in[8];
    const float* bf     = (const float*)d_in[9];
    const float* gamma  = (const float*)d_in[10];
    const float* beta   = (const float*)d_in[11];
    float* out = (float*)d_out;

    k1_kqx<<<512, 256>>>(x, vessel, wk, bk, wq, bq, wx, bx);
    k2_attn<<<1024, 128>>>();
    k3_stats<<<64, 256>>>(wf, bf, gamma, beta);
    k4_final<<<dim3(128,4), 128>>>(x, wf, bf, out);
}

// round 11
// speedup vs baseline: 1.8446x; 1.8446x over previous
#include <cuda_runtime.h>

#define HWc   4096
#define NPIX  16384   // B*H*W
#define Cc    256
#define CPc   32
#define EPSc  1e-5f

__device__ float g_km[NPIX*CPc];
__device__ float g_qm[NPIX*CPc];
__device__ float g_xm[NPIX*CPc];
__device__ float g_pre[NPIX*CPc];
__device__ float g_part[64*1056];
__device__ float g_ab[2*Cc];
__device__ unsigned int g_cnt;   // zero-init; self-resets each call

// ---------------------------------------------------------------------------
// K1: km/qm/xm = conv1x1(x, W) (+bias, km *= vessel), channel-last output
// grid (256 pixel-tiles of 64, 3 matrices), block 256   (R9 version, proven)
// ---------------------------------------------------------------------------
__global__ void k1_kqx(const float* __restrict__ x, const float* __restrict__ vessel,
                       const float* __restrict__ wk, const float* __restrict__ bk,
                       const float* __restrict__ wq, const float* __restrict__ bq,
                       const float* __restrict__ wx, const float* __restrict__ bx)
{
    __shared__ __align__(16) float xs[32][64];
    __shared__ __align__(16) float ws[32][32];
    int t  = threadIdx.x;
    int tx = t & 63;          // pixel within tile
    int ty = t >> 6;          // output group of 8 (4 groups -> 32 outs)
    int which = blockIdx.y;
    const float* W  = (which==0) ? wk : (which==1) ? wq : wx;
    const float* Bv = (which==0) ? bk : (which==1) ? bq : bx;
    float* outp     = (which==0) ? g_km : (which==1) ? g_qm : g_xm;

    int p0 = blockIdx.x * 64;
    const float* xb = x + (size_t)(p0 >> 12) * (Cc*HWc) + (p0 & (HWc-1));

    float acc[8];
#pragma unroll
    for (int i = 0; i < 8; ++i) acc[i] = 0.f;

    for (int c0 = 0; c0 < Cc; c0 += 32) {
#pragma unroll
        for (int i = 0; i < 8; ++i) {
            int idx = i*256 + t;
            int cc = idx >> 6, px = idx & 63;
            xs[cc][px] = xb[(size_t)(c0+cc)*HWc + px];
        }
#pragma unroll
        for (int i = 0; i < 4; ++i) {
            int idx = i*256 + t;
            int o = idx >> 5, cc = idx & 31;
            ws[cc][o] = W[o*Cc + c0 + cc];
        }
        __syncthreads();
#pragma unroll
        for (int cc = 0; cc < 32; ++cc) {
            float xv = xs[cc][tx];
            float4 wa = *(const float4*)&ws[cc][ty*8];
            float4 wb = *(const float4*)&ws[cc][ty*8+4];
            acc[0] += wa.x*xv; acc[1] += wa.y*xv; acc[2] += wa.z*xv; acc[3] += wa.w*xv;
            acc[4] += wb.x*xv; acc[5] += wb.y*xv; acc[6] += wb.z*xv; acc[7] += wb.w*xv;
        }
        __syncthreads();
    }
    int p = p0 + tx;
    float scale = (which==0) ? vessel[p] : 1.f;
    float* orow = outp + (size_t)p*CPc + ty*8;
#pragma unroll
    for (int i = 0; i < 8; ++i)
        orow[i] = (acc[i] + Bv[ty*8+i]) * scale;
}

// ---------------------------------------------------------------------------
// K2: multi-scale local attention, fused across nested windows (3<5<7<9).
// R9 version (proven): warp = 4 px, 8 lanes/px, 4 ch/lane; 1024 blocks x 128;
// no max-shift; exp + nested z sums fused into pass 1; pass 3 uses
// pre-combined coefficients selected at compile time.
// ---------------------------------------------------------------------------
__global__ void k2_attn()
{
    __shared__ float sc[4][81*4];   // per-warp exp buffer: [j][pixel-in-warp]
    int t    = threadIdx.x;
    int lane = t & 31, warp = t >> 5;
    int pxg  = lane >> 3;           // pixel in warp (0..3)
    int cg   = lane & 7;            // channel group (4 ch each)
    int p  = blockIdx.x * 16 + warp * 4 + pxg;
    int hw = p & (HWc-1);
    int h  = hw >> 6, w = hw & 63;

    const float* kmrow = g_km + (size_t)p*CPc + cg*4;
    const float* xmrow = g_xm + (size_t)p*CPc + cg*4;
    float4 q = *(const float4*)(g_qm + (size_t)p*CPc + cg*4);
    float* scp = sc[warp];

    // pass 1: scores -> e = exp(s), nested z sums in registers
    float z1=0.f, z2=0.f, z3=0.f, z4=0.f;
#pragma unroll
    for (int dy = -4; dy <= 4; ++dy) {
#pragma unroll
        for (int dx = -4; dx <= 4; ++dx) {
            int j = (dy+4)*9 + (dx+4);
            bool ok = ((unsigned)(h+dy) < 64u) && ((unsigned)(w+dx) < 64u);
            float4 km4 = make_float4(0.f,0.f,0.f,0.f);
            if (ok) km4 = *(const float4*)(kmrow + (dy*64+dx)*CPc);
            float s = km4.x*q.x + km4.y*q.y + km4.z*q.z + km4.w*q.w;
            s += __shfl_xor_sync(0xffffffffu, s, 1);
            s += __shfl_xor_sync(0xffffffffu, s, 2);
            s += __shfl_xor_sync(0xffffffffu, s, 4);
            float e = __expf(s);
            if (cg == 0) scp[j*4 + pxg] = e;
            const int ady = (dy < 0) ? -dy : dy;
            const int adx = (dx < 0) ? -dx : dx;
            const int a = (ady > adx) ? ady : adx;   // compile-time constant
            z4 += e;
            if (a <= 3) z3 += e;
            if (a <= 2) z2 += e;
            if (a <= 1) z1 += e;
        }
    }
    __syncwarp();

    float i4 = 1.0f/z4;
    float i3 = 1.0f/z3;
    float i2 = 1.0f/z2;
    float i1 = 1.0f/z1;
    float c4 = i4;
    float c3 = i4 + i3;
    float c2 = i4 + i3 + i2;
    float c1 = i4 + i3 + i2 + i1;

    // pass 3: weighted sweep, coefficient selected at compile time per offset
    float ax=0.f, ay=0.f, az=0.f, aw=0.f;
#pragma unroll
    for (int dy = -4; dy <= 4; ++dy) {
#pragma unroll
        for (int dx = -4; dx <= 4; ++dx) {
            int j = (dy+4)*9 + (dx+4);
            bool ok = ((unsigned)(h+dy) < 64u) && ((unsigned)(w+dx) < 64u);
            if (!ok) continue;   // OOB value == 0
            const int ady = (dy < 0) ? -dy : dy;
            const int adx = (dx < 0) ? -dx : dx;
            const int a = (ady > adx) ? ady : adx;   // compile-time constant
            float coef = (a <= 1) ? c1 : (a == 2) ? c2 : (a == 3) ? c3 : c4;
            float wj = scp[j*4 + pxg] * coef;
            float4 xm4 = *(const float4*)(xmrow + (dy*64+dx)*CPc);
            ax += wj*xm4.x; ay += wj*xm4.y; az += wj*xm4.z; aw += wj*xm4.w;
        }
    }
    *(float4*)(g_pre + (size_t)p*CPc + cg*4) = make_float4(ax, ay, az, aw);
}

// ---------------------------------------------------------------------------
// K3: fused BN-stats. Phase 1 (all 64 blocks): partial mean[32] + S[32][32]
// over a 256-pixel chunk. Phase 2 (last-arriving block, threadfence+counter):
// reduce partials, var_y = w^T S w - (w.mu)^2, fold into per-channel affine.
// ---------------------------------------------------------------------------
__global__ void k3_stats(const float* __restrict__ wf, const float* __restrict__ bf,
                         const float* __restrict__ gamma, const float* __restrict__ beta)
{
    __shared__ __align__(16) float ps[256*32];
    int t = threadIdx.x;
    size_t base = (size_t)blockIdx.x * 256 * 32;
#pragma unroll
    for (int i = 0; i < 32; ++i)
        ps[i*256 + t] = g_pre[base + i*256 + t];
    __syncthreads();

    int i  = t >> 3;
    int j4 = (t & 7) * 4;
    float s0=0.f, s1=0.f, s2=0.f, s3=0.f;
    for (int p = 0; p < 256; ++p) {
        float a  = ps[p*32 + i];
        float4 b = *(const float4*)&ps[p*32 + j4];
        s0 += a*b.x; s1 += a*b.y; s2 += a*b.z; s3 += a*b.w;
    }
    float* part = g_part + blockIdx.x * 1056;
    part[32 + i*32 + j4 + 0] = s0;
    part[32 + i*32 + j4 + 1] = s1;
    part[32 + i*32 + j4 + 2] = s2;
    part[32 + i*32 + j4 + 3] = s3;
    if (t < 32) {
        float mm = 0.f;
        for (int p = 0; p < 256; ++p) mm += ps[p*32 + t];
        part[t] = mm;
    }
    __threadfence();
    __syncthreads();

    __shared__ unsigned int amLast;
    if (t == 0) amLast = atomicAdd(&g_cnt, 1u);
    __syncthreads();
    if (amLast != 63u) return;

    float* S = ps;   // reuse smem
    for (int e = t; e < 1056; e += 256) {
        float s = 0.f;
#pragma unroll
        for (int b = 0; b < 64; ++b) s += g_part[b*1056 + e];
        S[e] = s * (1.0f/16384.0f);
    }
    __syncthreads();

    {
        float wreg[32];
#pragma unroll
        for (int c = 0; c < 32; ++c) wreg[c] = wf[t*32 + c];
        float wmu = 0.f;
#pragma unroll
        for (int c = 0; c < 32; ++c) wmu += wreg[c] * S[c];
        float qf = 0.f;
        for (int c = 0; c < 32; ++c) {
            float tc = 0.f;
#pragma unroll
            for (int d = 0; d < 32; ++d) tc += S[32 + c*32 + d] * wreg[d];
            qf += wreg[c] * tc;
        }
        float var   = qf - wmu*wmu;
        float meanY = wmu + bf[t];
        float a = gamma[t] * rsqrtf(var + EPSc);
        g_ab[t]       = a;
        g_ab[256 + t] = beta[t] - a * meanY;
    }
    if (t == 0) g_cnt = 0u;   // reset for next graph replay
}

// ---------------------------------------------------------------------------
// K4: out = x + a[co]*(wf.pre) + bb[co]  (bb = a*bf + beta - a*meanY, folded)
// grid (128 px-tiles of 128, 4 co-groups of 64), block 128 — same traffic as
// R6/R9, but LDS issue count cut 4x:
//  - weights TRANSPOSED in smem wsT[c][co] (pad 68) -> inner loop does
//    float4 broadcast LDS per 4 outputs (512 LDS.128 vs 2048 LDS.32)
//  - pre tile staged in padded smem sp[px][33] so the c-loop stays rolled
//    (no dynamically-indexed register array), accumulators y[64] in regs.
// FMA floor (~8us) becomes binding instead of LDS issue floor (~16us).
// ---------------------------------------------------------------------------
__global__ void __launch_bounds__(128) k4_final(
    const float* __restrict__ x, const float* __restrict__ wf,
    const float* __restrict__ bf, float* __restrict__ out)
{
    __shared__ __align__(16) float wsT[32][68];   // [c][co], padded
    __shared__ float sp[128][33];                 // [px][c], padded
    __shared__ float as[64], bbs[64];
    int t = threadIdx.x;
    int cog = blockIdx.y * 64;

    // stage + transpose weights: wf[cog+co][c] -> wsT[c][co]
#pragma unroll
    for (int i = 0; i < 16; ++i) {
        int e = i*128 + t;
        int co = e >> 5, c = e & 31;
        wsT[c][co] = wf[(size_t)(cog+co)*32 + c];
    }
    if (t < 64) {
        float a = g_ab[cog+t];
        as[t]  = a;
        bbs[t] = g_ab[256+cog+t] + a * bf[cog+t];
    }

    // stage pre tile: 128 px x 32 ch (float4 gmem loads, padded smem)
    int p0 = blockIdx.x * 128;
    const float4* pre4 = (const float4*)(g_pre + (size_t)p0*32);
#pragma unroll
    for (int i = 0; i < 8; ++i) {
        int idx = i*128 + t;          // 1024 float4s
        int px = idx >> 3, c4 = idx & 7;
        float4 v = pre4[idx];
        sp[px][c4*4+0] = v.x; sp[px][c4*4+1] = v.y;
        sp[px][c4*4+2] = v.z; sp[px][c4*4+3] = v.w;
    }
    __syncthreads();

    float y[64];
#pragma unroll
    for (int co = 0; co < 64; ++co) y[co] = 0.f;

    const float* myrow = &sp[t][0];
#pragma unroll 4
    for (int c = 0; c < 32; ++c) {
        float xv = myrow[c];
#pragma unroll
        for (int g = 0; g < 16; ++g) {
            float4 w4 = *(const float4*)&wsT[c][g*4];
            y[g*4+0] += w4.x*xv;
            y[g*4+1] += w4.y*xv;
            y[g*4+2] += w4.z*xv;
            y[g*4+3] += w4.w*xv;
        }
    }

    int p = p0 + t;
    int b = p >> 12, hw = p & 4095;
    const float* xrow = x   + (size_t)b*(Cc*HWc) + hw;
    float*       orow = out + (size_t)b*(Cc*HWc) + hw;
#pragma unroll
    for (int co = 0; co < 64; ++co) {
        size_t off = (size_t)(cog + co) * HWc;
        orow[off] = xrow[off] + as[co]*y[co] + bbs[co];
    }
}

// ---------------------------------------------------------------------------
extern "C" void kernel_launch(void* const* d_in, const int* in_sizes, int n_in,
                              void* d_out, int out_size)
{
    const float* x      = (const float*)d_in[0];
    const float* vessel = (const float*)d_in[1];
    const float* wk     = (const float*)d_in[2];
    const float* bk     = (const float*)d_in[3];
    const float* wq     = (const float*)d_in[4];
    const float* bq     = (const float*)d_in[5];
    const float* wx     = (const float*)d_in[6];
    const float* bx     = (const float*)d_in[7];
    const float* wf     = (const float*)d_in[8];
    const float* bf     = (const float*)d_in[9];
    const float* gamma  = (const float*)d_in[10];
    const float* beta   = (const float*)d_in[11];
    float* out = (float*)d_out;

    k1_kqx<<<dim3(256,3), 256>>>(x, vessel, wk, bk, wq, bq, wx, bx);
    k2_attn<<<1024, 128>>>();
    k3_stats<<<64, 256>>>(wf, bf, gamma, beta);
    k4_final<<<dim3(128,4), 128>>>(x, wf, bf, out);
}

// round 15
// speedup vs baseline: 2.9493x; 1.5989x over previous
#include <cuda_runtime.h>
#include <cuda_bf16.h>
#include <cstdint>

#define HWc   4096
#define NPIX  16384   // B*H*W
#define Cc    256
#define CPc   32
#define EPSc  1e-5f

__device__ float g_km[NPIX*CPc];
__device__ float g_qm[NPIX*CPc];
__device__ float g_xm[NPIX*CPc];
__device__ float g_pre[NPIX*CPc];
__device__ float g_part[64*1056];
__device__ float g_ab[2*Cc];
__device__ unsigned int g_cnt;   // zero-init; self-resets each call

static __device__ __forceinline__ uint32_t smem_u32(const void* p) {
    uint32_t a;
    asm("{ .reg .u64 tmp; cvta.to.shared.u64 tmp, %1; cvt.u32.u64 %0, tmp; }"
        : "=r"(a) : "l"(p));
    return a;
}

#define LDMX4(r0,r1,r2,r3,addr) \
    asm volatile("ldmatrix.sync.aligned.m8n8.x4.shared.b16 {%0,%1,%2,%3}, [%4];" \
        : "=r"(r0),"=r"(r1),"=r"(r2),"=r"(r3) : "r"(addr))
#define LDMX2(r0,r1,addr) \
    asm volatile("ldmatrix.sync.aligned.m8n8.x2.shared.b16 {%0,%1}, [%2];" \
        : "=r"(r0),"=r"(r1) : "r"(addr))
#define MMA16816(C,a0,a1,a2,a3,b0,b1) \
    asm volatile("mma.sync.aligned.m16n8k16.row.col.f32.bf16.bf16.f32 " \
        "{%0,%1,%2,%3}, {%4,%5,%6,%7}, {%8,%9}, {%0,%1,%2,%3};" \
        : "+f"((C)[0]), "+f"((C)[1]), "+f"((C)[2]), "+f"((C)[3]) \
        : "r"(a0),"r"(a1),"r"(a2),"r"(a3), "r"(b0),"r"(b1))

// ---------------------------------------------------------------------------
// K1 (HMMA mma.sync): km/qm/xm = conv1x1 via bf16 split-precision tensor-core
// GEMM. Block = 64 pixels x 96 outputs (k|q|x fused), 256 thr = 8 warps,
// warp = 16m x 48n. K chunked at 64; smem stride 72 bf16 (144B) => ldmatrix
// conflict-free. D = Ah*Bh + Al*Bh + Ah*Bl (lo*lo ~2^-32, dropped).
// ---------------------------------------------------------------------------
__global__ void __launch_bounds__(256) k1_kqx_mma(
    const float* __restrict__ x, const float* __restrict__ vessel,
    const float* __restrict__ wk, const float* __restrict__ bk,
    const float* __restrict__ wq, const float* __restrict__ bq,
    const float* __restrict__ wx, const float* __restrict__ bx)
{
    __shared__ __align__(16) __nv_bfloat16 Ah[64*72], Al[64*72];
    __shared__ __align__(16) __nv_bfloat16 Bh[96*72], Bl[96*72];
    __shared__ float bs[96], vs[64];

    int t = threadIdx.x;
    int w = t >> 5, lane = t & 31;
    int p0 = blockIdx.x * 64;
    const float* xb = x + (size_t)(p0 >> 12)*(Cc*HWc) + (p0 & (HWc-1));

    if (t < 96) bs[t] = (t < 32) ? bk[t] : (t < 64) ? bq[t-32] : bx[t-64];
    if (t < 64) vs[t] = vessel[p0 + t];

    int ms = w & 3;          // m-strip: rows ms*16..+15
    int nh = w >> 2;         // n-half: cols nh*48..+47
    int m0 = ms * 16;

    float acc[6][4];
#pragma unroll
    for (int i = 0; i < 6; ++i)
#pragma unroll
        for (int j = 0; j < 4; ++j) acc[i][j] = 0.f;

    // per-lane ldmatrix row bases (element offsets within A / B layouts)
    int a_row = m0 + (lane & 15);
    int a_col = ((lane >> 4) << 3);          // 0 or 8
    int b_row = lane & 7;
    int b_col = ((lane >> 3) & 1) << 3;      // 0 or 8 (lanes 0-15 used by x2)

    uint32_t AhB = smem_u32(Ah), AlB = smem_u32(Al);
    uint32_t BhB = smem_u32(Bh), BlB = smem_u32(Bl);
    uint32_t aOff = (uint32_t)(a_row*72 + a_col) * 2u;
    uint32_t bOffL = (uint32_t)(b_row*72 + b_col) * 2u;

    for (int c0 = 0; c0 < 256; c0 += 64) {
        __syncthreads();
        // stage A: 64 px x 64 ch, split hi/lo. A[m=px][k=cc]
#pragma unroll
        for (int i = 0; i < 16; ++i) {
            int idx = i*256 + t;
            int px = idx & 63, cc = idx >> 6;
            float v = xb[(size_t)(c0+cc)*HWc + px];
            __nv_bfloat16 h = __float2bfloat16(v);
            __nv_bfloat16 l = __float2bfloat16(v - __bfloat162float(h));
            Ah[px*72 + cc] = h;
            Al[px*72 + cc] = l;
        }
        // stage B: 96 outs x 64 ch. B[n=o][k]
#pragma unroll
        for (int i = 0; i < 24; ++i) {
            int idx = i*256 + t;
            int k = idx & 63, o = idx >> 6;
            const float* W = (o < 32) ? wk : (o < 64) ? wq : wx;
            float v = W[(o & 31)*256 + c0 + k];
            __nv_bfloat16 h = __float2bfloat16(v);
            __nv_bfloat16 l = __float2bfloat16(v - __bfloat162float(h));
            Bh[o*72 + k] = h;
            Bl[o*72 + k] = l;
        }
        __syncthreads();

#pragma unroll
        for (int ks = 0; ks < 4; ++ks) {
            uint32_t kByte = (uint32_t)(ks*16) * 2u;
            uint32_t ah0,ah1,ah2,ah3, al0,al1,al2,al3;
            LDMX4(ah0,ah1,ah2,ah3, AhB + aOff + kByte);
            LDMX4(al0,al1,al2,al3, AlB + aOff + kByte);
#pragma unroll
            for (int nt = 0; nt < 6; ++nt) {
                uint32_t nByte = (uint32_t)((nh*48 + nt*8)*72) * 2u;
                uint32_t bh0,bh1, bl0,bl1;
                LDMX2(bh0,bh1, BhB + bOffL + nByte + kByte);
                LDMX2(bl0,bl1, BlB + bOffL + nByte + kByte);
                MMA16816(acc[nt], ah0,ah1,ah2,ah3, bh0,bh1);
                MMA16816(acc[nt], al0,al1,al2,al3, bh0,bh1);
                MMA16816(acc[nt], ah0,ah1,ah2,ah3, bl0,bl1);
            }
        }
    }

    // epilogue: c-frag -> bias, vessel (km only), channel-last float2 stores
    int r  = lane >> 2;              // 0..7
    int c2 = (lane & 3) * 2;         // even col in n-tile
    int px0 = m0 + r, px1 = m0 + r + 8;
    int pA = p0 + px0, pB = p0 + px1;
    float v0 = vs[px0], v1 = vs[px1];
#pragma unroll
    for (int nt = 0; nt < 6; ++nt) {
        int n0  = nh*48 + nt*8;
        int mat = n0 >> 5;
        int ch  = (n0 + c2) & 31;
        float* dst = (mat == 0) ? g_km : (mat == 1) ? g_qm : g_xm;
        float s0 = (mat == 0) ? v0 : 1.f;
        float s1 = (mat == 0) ? v1 : 1.f;
        float b0 = bs[n0 + c2], b1 = bs[n0 + c2 + 1];
        float2 o0 = make_float2((acc[nt][0] + b0) * s0, (acc[nt][1] + b1) * s0);
        float2 o1 = make_float2((acc[nt][2] + b0) * s1, (acc[nt][3] + b1) * s1);
        *(float2*)(dst + (size_t)pA*CPc + ch) = o0;
        *(float2*)(dst + (size_t)pB*CPc + ch) = o1;
    }
}

// ---------------------------------------------------------------------------
// K2: multi-scale local attention (R9/R11 proven version, unchanged)
// ---------------------------------------------------------------------------
__global__ void k2_attn()
{
    __shared__ float sc[4][81*4];
    int t    = threadIdx.x;
    int lane = t & 31, warp = t >> 5;
    int pxg  = lane >> 3;
    int cg   = lane & 7;
    int p  = blockIdx.x * 16 + warp * 4 + pxg;
    int hw = p & (HWc-1);
    int h  = hw >> 6, w = hw & 63;

    const float* kmrow = g_km + (size_t)p*CPc + cg*4;
    const float* xmrow = g_xm + (size_t)p*CPc + cg*4;
    float4 q = *(const float4*)(g_qm + (size_t)p*CPc + cg*4);
    float* scp = sc[warp];

    float z1=0.f, z2=0.f, z3=0.f, z4=0.f;
#pragma unroll
    for (int dy = -4; dy <= 4; ++dy) {
#pragma unroll
        for (int dx = -4; dx <= 4; ++dx) {
            int j = (dy+4)*9 + (dx+4);
            bool ok = ((unsigned)(h+dy) < 64u) && ((unsigned)(w+dx) < 64u);
            float4 km4 = make_float4(0.f,0.f,0.f,0.f);
            if (ok) km4 = *(const float4*)(kmrow + (dy*64+dx)*CPc);
            float s = km4.x*q.x + km4.y*q.y + km4.z*q.z + km4.w*q.w;
            s += __shfl_xor_sync(0xffffffffu, s, 1);
            s += __shfl_xor_sync(0xffffffffu, s, 2);
            s += __shfl_xor_sync(0xffffffffu, s, 4);
            float e = __expf(s);
            if (cg == 0) scp[j*4 + pxg] = e;
            const int ady = (dy < 0) ? -dy : dy;
            const int adx = (dx < 0) ? -dx : dx;
            const int a = (ady > adx) ? ady : adx;
            z4 += e;
            if (a <= 3) z3 += e;
            if (a <= 2) z2 += e;
            if (a <= 1) z1 += e;
        }
    }
    __syncwarp();

    float i4 = 1.0f/z4, i3 = 1.0f/z3, i2 = 1.0f/z2, i1 = 1.0f/z1;
    float c4 = i4, c3 = i4+i3, c2 = i4+i3+i2, c1 = i4+i3+i2+i1;

    float ax=0.f, ay=0.f, az=0.f, aw=0.f;
#pragma unroll
    for (int dy = -4; dy <= 4; ++dy) {
#pragma unroll
        for (int dx = -4; dx <= 4; ++dx) {
            int j = (dy+4)*9 + (dx+4);
            bool ok = ((unsigned)(h+dy) < 64u) && ((unsigned)(w+dx) < 64u);
            if (!ok) continue;
            const int ady = (dy < 0) ? -dy : dy;
            const int adx = (dx < 0) ? -dx : dx;
            const int a = (ady > adx) ? ady : adx;
            float coef = (a <= 1) ? c1 : (a == 2) ? c2 : (a == 3) ? c3 : c4;
            float wj = scp[j*4 + pxg] * coef;
            float4 xm4 = *(const float4*)(xmrow + (dy*64+dx)*CPc);
            ax += wj*xm4.x; ay += wj*xm4.y; az += wj*xm4.z; aw += wj*xm4.w;
        }
    }
    *(float4*)(g_pre + (size_t)p*CPc + cg*4) = make_float4(ax, ay, az, aw);
}

// ---------------------------------------------------------------------------
// K3: fused BN-stats (unchanged)
// ---------------------------------------------------------------------------
__global__ void k3_stats(const float* __restrict__ wf, const float* __restrict__ bf,
                         const float* __restrict__ gamma, const float* __restrict__ beta)
{
    __shared__ __align__(16) float ps[256*32];
    int t = threadIdx.x;
    size_t base = (size_t)blockIdx.x * 256 * 32;
#pragma unroll
    for (int i = 0; i < 32; ++i)
        ps[i*256 + t] = g_pre[base + i*256 + t];
    __syncthreads();

    int i  = t >> 3;
    int j4 = (t & 7) * 4;
    float s0=0.f, s1=0.f, s2=0.f, s3=0.f;
    for (int p = 0; p < 256; ++p) {
        float a  = ps[p*32 + i];
        float4 b = *(const float4*)&ps[p*32 + j4];
        s0 += a*b.x; s1 += a*b.y; s2 += a*b.z; s3 += a*b.w;
    }
    float* part = g_part + blockIdx.x * 1056;
    part[32 + i*32 + j4 + 0] = s0;
    part[32 + i*32 + j4 + 1] = s1;
    part[32 + i*32 + j4 + 2] = s2;
    part[32 + i*32 + j4 + 3] = s3;
    if (t < 32) {
        float mm = 0.f;
        for (int p = 0; p < 256; ++p) mm += ps[p*32 + t];
        part[t] = mm;
    }
    __threadfence();
    __syncthreads();

    __shared__ unsigned int amLast;
    if (t == 0) amLast = atomicAdd(&g_cnt, 1u);
    __syncthreads();
    if (amLast != 63u) return;

    float* S = ps;
    for (int e = t; e < 1056; e += 256) {
        float s = 0.f;
#pragma unroll
        for (int b = 0; b < 64; ++b) s += g_part[b*1056 + e];
        S[e] = s * (1.0f/16384.0f);
    }
    __syncthreads();

    {
        float wreg[32];
#pragma unroll
        for (int c = 0; c < 32; ++c) wreg[c] = wf[t*32 + c];
        float wmu = 0.f;
#pragma unroll
        for (int c = 0; c < 32; ++c) wmu += wreg[c] * S[c];
        float qf = 0.f;
        for (int c = 0; c < 32; ++c) {
            float tc = 0.f;
#pragma unroll
            for (int d = 0; d < 32; ++d) tc += S[32 + c*32 + d] * wreg[d];
            qf += wreg[c] * tc;
        }
        float var   = qf - wmu*wmu;
        float meanY = wmu + bf[t];
        float a = gamma[t] * rsqrtf(var + EPSc);
        g_ab[t]       = a;
        g_ab[256 + t] = beta[t] - a * meanY;
    }
    if (t == 0) g_cnt = 0u;
}

// ---------------------------------------------------------------------------
// K4: out = x + a[co]*(wf.pre) + bb[co]  (R11 transposed-weight version)
// ---------------------------------------------------------------------------
__global__ void __launch_bounds__(128) k4_final(
    const float* __restrict__ x, const float* __restrict__ wf,
    const float* __restrict__ bf, float* __restrict__ out)
{
    __shared__ __align__(16) float wsT[32][68];
    __shared__ float sp[128][33];
    __shared__ float as[64], bbs[64];
    int t = threadIdx.x;
    int cog = blockIdx.y * 64;

#pragma unroll
    for (int i = 0; i < 16; ++i) {
        int e = i*128 + t;
        int co = e >> 5, c = e & 31;
        wsT[c][co] = wf[(size_t)(cog+co)*32 + c];
    }
    if (t < 64) {
        float a = g_ab[cog+t];
        as[t]  = a;
        bbs[t] = g_ab[256+cog+t] + a * bf[cog+t];
    }

    int p0 = blockIdx.x * 128;
    const float4* pre4 = (const float4*)(g_pre + (size_t)p0*32);
#pragma unroll
    for (int i = 0; i < 8; ++i) {
        int idx = i*128 + t;
        int px = idx >> 3, c4 = idx & 7;
        float4 v = pre4[idx];
        sp[px][c4*4+0] = v.x; sp[px][c4*4+1] = v.y;
        sp[px][c4*4+2] = v.z; sp[px][c4*4+3] = v.w;
    }
    __syncthreads();

    float y[64];
#pragma unroll
    for (int co = 0; co < 64; ++co) y[co] = 0.f;

    const float* myrow = &sp[t][0];
#pragma unroll 4
    for (int c = 0; c < 32; ++c) {
        float xv = myrow[c];
#pragma unroll
        for (int g = 0; g < 16; ++g) {
            float4 w4 = *(const float4*)&wsT[c][g*4];
            y[g*4+0] += w4.x*xv;
            y[g*4+1] += w4.y*xv;
            y[g*4+2] += w4.z*xv;
            y[g*4+3] += w4.w*xv;
        }
    }

    int p = p0 + t;
    int b = p >> 12, hw = p & 4095;
    const float* xrow = x   + (size_t)b*(Cc*HWc) + hw;
    float*       orow = out + (size_t)b*(Cc*HWc) + hw;
#pragma unroll
    for (int co = 0; co < 64; ++co) {
        size_t off = (size_t)(cog + co) * HWc;
        orow[off] = xrow[off] + as[co]*y[co] + bbs[co];
    }
}

// ---------------------------------------------------------------------------
extern "C" void kernel_launch(void* const* d_in, const int* in_sizes, int n_in,
                              void* d_out, int out_size)
{
    const float* x      = (const float*)d_in[0];
    const float* vessel = (const float*)d_in[1];
    const float* wk     = (const float*)d_in[2];
    const float* bk     = (const float*)d_in[3];
    const float* wq     = (const float*)d_in[4];
    const float* bq     = (const float*)d_in[5];
    const float* wx     = (const float*)d_in[6];
    const float* bx     = (const float*)d_in[7];
    const float* wf     = (const float*)d_in[8];
    const float* bf     = (const float*)d_in[9];
    const float* gamma  = (const float*)d_in[10];
    const float* beta   = (const float*)d_in[11];
    float* out = (float*)d_out;

    k1_kqx_mma<<<256, 256>>>(x, vessel, wk, bk, wq, bq, wx, bx);
    k2_attn<<<1024, 128>>>();
    k3_stats<<<64, 256>>>(wf, bf, gamma, beta);
    k4_final<<<dim3(128,4), 128>>>(x, wf, bf, out);
}

// round 16
// speedup vs baseline: 3.0004x; 1.0173x over previous
#include <cuda_runtime.h>
#include <cuda_bf16.h>
#include <cstdint>

#define HWc   4096
#define NPIX  16384   // B*H*W
#define Cc    256
#define CPc   32
#define EPSc  1e-5f

__device__ float g_km[NPIX*CPc];
__device__ float g_qm[NPIX*CPc];
__device__ float g_xm[NPIX*CPc];
__device__ float g_pre[NPIX*CPc];
__device__ float g_part[64*1056];
__device__ float g_ab[2*Cc];
__device__ unsigned int g_cnt;   // zero-init; self-resets each call

static __device__ __forceinline__ uint32_t smem_u32(const void* p) {
    uint32_t a;
    asm("{ .reg .u64 tmp; cvta.to.shared.u64 tmp, %1; cvt.u32.u64 %0, tmp; }"
        : "=r"(a) : "l"(p));
    return a;
}

#define LDMX4(r0,r1,r2,r3,addr) \
    asm volatile("ldmatrix.sync.aligned.m8n8.x4.shared.b16 {%0,%1,%2,%3}, [%4];" \
        : "=r"(r0),"=r"(r1),"=r"(r2),"=r"(r3) : "r"(addr))
#define LDMX2(r0,r1,addr) \
    asm volatile("ldmatrix.sync.aligned.m8n8.x2.shared.b16 {%0,%1}, [%2];" \
        : "=r"(r0),"=r"(r1) : "r"(addr))
#define MMA16816(C,a0,a1,a2,a3,b0,b1) \
    asm volatile("mma.sync.aligned.m16n8k16.row.col.f32.bf16.bf16.f32 " \
        "{%0,%1,%2,%3}, {%4,%5,%6,%7}, {%8,%9}, {%0,%1,%2,%3};" \
        : "+f"((C)[0]), "+f"((C)[1]), "+f"((C)[2]), "+f"((C)[3]) \
        : "r"(a0),"r"(a1),"r"(a2),"r"(a3), "r"(b0),"r"(b1))

// ---------------------------------------------------------------------------
// K1 (HMMA mma.sync): km/qm/xm = conv1x1 via bf16 split-precision tensor-core
// GEMM.  (R15 version, PROVEN: 131->82.7us)
// ---------------------------------------------------------------------------
__global__ void __launch_bounds__(256) k1_kqx_mma(
    const float* __restrict__ x, const float* __restrict__ vessel,
    const float* __restrict__ wk, const float* __restrict__ bk,
    const float* __restrict__ wq, const float* __restrict__ bq,
    const float* __restrict__ wx, const float* __restrict__ bx)
{
    __shared__ __align__(16) __nv_bfloat16 Ah[64*72], Al[64*72];
    __shared__ __align__(16) __nv_bfloat16 Bh[96*72], Bl[96*72];
    __shared__ float bs[96], vs[64];

    int t = threadIdx.x;
    int w = t >> 5, lane = t & 31;
    int p0 = blockIdx.x * 64;
    const float* xb = x + (size_t)(p0 >> 12)*(Cc*HWc) + (p0 & (HWc-1));

    if (t < 96) bs[t] = (t < 32) ? bk[t] : (t < 64) ? bq[t-32] : bx[t-64];
    if (t < 64) vs[t] = vessel[p0 + t];

    int ms = w & 3;
    int nh = w >> 2;
    int m0 = ms * 16;

    float acc[6][4];
#pragma unroll
    for (int i = 0; i < 6; ++i)
#pragma unroll
        for (int j = 0; j < 4; ++j) acc[i][j] = 0.f;

    int a_row = m0 + (lane & 15);
    int a_col = ((lane >> 4) << 3);
    int b_row = lane & 7;
    int b_col = ((lane >> 3) & 1) << 3;

    uint32_t AhB = smem_u32(Ah), AlB = smem_u32(Al);
    uint32_t BhB = smem_u32(Bh), BlB = smem_u32(Bl);
    uint32_t aOff = (uint32_t)(a_row*72 + a_col) * 2u;
    uint32_t bOffL = (uint32_t)(b_row*72 + b_col) * 2u;

    for (int c0 = 0; c0 < 256; c0 += 64) {
        __syncthreads();
#pragma unroll
        for (int i = 0; i < 16; ++i) {
            int idx = i*256 + t;
            int px = idx & 63, cc = idx >> 6;
            float v = xb[(size_t)(c0+cc)*HWc + px];
            __nv_bfloat16 h = __float2bfloat16(v);
            __nv_bfloat16 l = __float2bfloat16(v - __bfloat162float(h));
            Ah[px*72 + cc] = h;
            Al[px*72 + cc] = l;
        }
#pragma unroll
        for (int i = 0; i < 24; ++i) {
            int idx = i*256 + t;
            int k = idx & 63, o = idx >> 6;
            const float* W = (o < 32) ? wk : (o < 64) ? wq : wx;
            float v = W[(o & 31)*256 + c0 + k];
            __nv_bfloat16 h = __float2bfloat16(v);
            __nv_bfloat16 l = __float2bfloat16(v - __bfloat162float(h));
            Bh[o*72 + k] = h;
            Bl[o*72 + k] = l;
        }
        __syncthreads();

#pragma unroll
        for (int ks = 0; ks < 4; ++ks) {
            uint32_t kByte = (uint32_t)(ks*16) * 2u;
            uint32_t ah0,ah1,ah2,ah3, al0,al1,al2,al3;
            LDMX4(ah0,ah1,ah2,ah3, AhB + aOff + kByte);
            LDMX4(al0,al1,al2,al3, AlB + aOff + kByte);
#pragma unroll
            for (int nt = 0; nt < 6; ++nt) {
                uint32_t nByte = (uint32_t)((nh*48 + nt*8)*72) * 2u;
                uint32_t bh0,bh1, bl0,bl1;
                LDMX2(bh0,bh1, BhB + bOffL + nByte + kByte);
                LDMX2(bl0,bl1, BlB + bOffL + nByte + kByte);
                MMA16816(acc[nt], ah0,ah1,ah2,ah3, bh0,bh1);
                MMA16816(acc[nt], al0,al1,al2,al3, bh0,bh1);
                MMA16816(acc[nt], ah0,ah1,ah2,ah3, bl0,bl1);
            }
        }
    }

    int r  = lane >> 2;
    int c2 = (lane & 3) * 2;
    int px0 = m0 + r, px1 = m0 + r + 8;
    int pA = p0 + px0, pB = p0 + px1;
    float v0 = vs[px0], v1 = vs[px1];
#pragma unroll
    for (int nt = 0; nt < 6; ++nt) {
        int n0  = nh*48 + nt*8;
        int mat = n0 >> 5;
        int ch  = (n0 + c2) & 31;
        float* dst = (mat == 0) ? g_km : (mat == 1) ? g_qm : g_xm;
        float s0 = (mat == 0) ? v0 : 1.f;
        float s1 = (mat == 0) ? v1 : 1.f;
        float b0 = bs[n0 + c2], b1 = bs[n0 + c2 + 1];
        float2 o0 = make_float2((acc[nt][0] + b0) * s0, (acc[nt][1] + b1) * s0);
        float2 o1 = make_float2((acc[nt][2] + b0) * s1, (acc[nt][3] + b1) * s1);
        *(float2*)(dst + (size_t)pA*CPc + ch) = o0;
        *(float2*)(dst + (size_t)pB*CPc + ch) = o1;
    }
}

// ---------------------------------------------------------------------------
// K2: multi-scale local attention (proven version, unchanged)
// ---------------------------------------------------------------------------
__global__ void k2_attn()
{
    __shared__ float sc[4][81*4];
    int t    = threadIdx.x;
    int lane = t & 31, warp = t >> 5;
    int pxg  = lane >> 3;
    int cg   = lane & 7;
    int p  = blockIdx.x * 16 + warp * 4 + pxg;
    int hw = p & (HWc-1);
    int h  = hw >> 6, w = hw & 63;

    const float* kmrow = g_km + (size_t)p*CPc + cg*4;
    const float* xmrow = g_xm + (size_t)p*CPc + cg*4;
    float4 q = *(const float4*)(g_qm + (size_t)p*CPc + cg*4);
    float* scp = sc[warp];

    float z1=0.f, z2=0.f, z3=0.f, z4=0.f;
#pragma unroll
    for (int dy = -4; dy <= 4; ++dy) {
#pragma unroll
        for (int dx = -4; dx <= 4; ++dx) {
            int j = (dy+4)*9 + (dx+4);
            bool ok = ((unsigned)(h+dy) < 64u) && ((unsigned)(w+dx) < 64u);
            float4 km4 = make_float4(0.f,0.f,0.f,0.f);
            if (ok) km4 = *(const float4*)(kmrow + (dy*64+dx)*CPc);
            float s = km4.x*q.x + km4.y*q.y + km4.z*q.z + km4.w*q.w;
            s += __shfl_xor_sync(0xffffffffu, s, 1);
            s += __shfl_xor_sync(0xffffffffu, s, 2);
            s += __shfl_xor_sync(0xffffffffu, s, 4);
            float e = __expf(s);
            if (cg == 0) scp[j*4 + pxg] = e;
            const int ady = (dy < 0) ? -dy : dy;
            const int adx = (dx < 0) ? -dx : dx;
            const int a = (ady > adx) ? ady : adx;
            z4 += e;
            if (a <= 3) z3 += e;
            if (a <= 2) z2 += e;
            if (a <= 1) z1 += e;
        }
    }
    __syncwarp();

    float i4 = 1.0f/z4, i3 = 1.0f/z3, i2 = 1.0f/z2, i1 = 1.0f/z1;
    float c4 = i4, c3 = i4+i3, c2 = i4+i3+i2, c1 = i4+i3+i2+i1;

    float ax=0.f, ay=0.f, az=0.f, aw=0.f;
#pragma unroll
    for (int dy = -4; dy <= 4; ++dy) {
#pragma unroll
        for (int dx = -4; dx <= 4; ++dx) {
            int j = (dy+4)*9 + (dx+4);
            bool ok = ((unsigned)(h+dy) < 64u) && ((unsigned)(w+dx) < 64u);
            if (!ok) continue;
            const int ady = (dy < 0) ? -dy : dy;
            const int adx = (dx < 0) ? -dx : dx;
            const int a = (ady > adx) ? ady : adx;
            float coef = (a <= 1) ? c1 : (a == 2) ? c2 : (a == 3) ? c3 : c4;
            float wj = scp[j*4 + pxg] * coef;
            float4 xm4 = *(const float4*)(xmrow + (dy*64+dx)*CPc);
            ax += wj*xm4.x; ay += wj*xm4.y; az += wj*xm4.z; aw += wj*xm4.w;
        }
    }
    *(float4*)(g_pre + (size_t)p*CPc + cg*4) = make_float4(ax, ay, az, aw);
}

// ---------------------------------------------------------------------------
// K3: fused BN-stats (unchanged)
// ---------------------------------------------------------------------------
__global__ void k3_stats(const float* __restrict__ wf, const float* __restrict__ bf,
                         const float* __restrict__ gamma, const float* __restrict__ beta)
{
    __shared__ __align__(16) float ps[256*32];
    int t = threadIdx.x;
    size_t base = (size_t)blockIdx.x * 256 * 32;
#pragma unroll
    for (int i = 0; i < 32; ++i)
        ps[i*256 + t] = g_pre[base + i*256 + t];
    __syncthreads();

    int i  = t >> 3;
    int j4 = (t & 7) * 4;
    float s0=0.f, s1=0.f, s2=0.f, s3=0.f;
    for (int p = 0; p < 256; ++p) {
        float a  = ps[p*32 + i];
        float4 b = *(const float4*)&ps[p*32 + j4];
        s0 += a*b.x; s1 += a*b.y; s2 += a*b.z; s3 += a*b.w;
    }
    float* part = g_part + blockIdx.x * 1056;
    part[32 + i*32 + j4 + 0] = s0;
    part[32 + i*32 + j4 + 1] = s1;
    part[32 + i*32 + j4 + 2] = s2;
    part[32 + i*32 + j4 + 3] = s3;
    if (t < 32) {
        float mm = 0.f;
        for (int p = 0; p < 256; ++p) mm += ps[p*32 + t];
        part[t] = mm;
    }
    __threadfence();
    __syncthreads();

    __shared__ unsigned int amLast;
    if (t == 0) amLast = atomicAdd(&g_cnt, 1u);
    __syncthreads();
    if (amLast != 63u) return;

    float* S = ps;
    for (int e = t; e < 1056; e += 256) {
        float s = 0.f;
#pragma unroll
        for (int b = 0; b < 64; ++b) s += g_part[b*1056 + e];
        S[e] = s * (1.0f/16384.0f);
    }
    __syncthreads();

    {
        float wreg[32];
#pragma unroll
        for (int c = 0; c < 32; ++c) wreg[c] = wf[t*32 + c];
        float wmu = 0.f;
#pragma unroll
        for (int c = 0; c < 32; ++c) wmu += wreg[c] * S[c];
        float qf = 0.f;
        for (int c = 0; c < 32; ++c) {
            float tc = 0.f;
#pragma unroll
            for (int d = 0; d < 32; ++d) tc += S[32 + c*32 + d] * wreg[d];
            qf += wreg[c] * tc;
        }
        float var   = qf - wmu*wmu;
        float meanY = wmu + bf[t];
        float a = gamma[t] * rsqrtf(var + EPSc);
        g_ab[t]       = a;
        g_ab[256 + t] = beta[t] - a * meanY;
    }
    if (t == 0) g_cnt = 0u;
}

// ---------------------------------------------------------------------------
// K4 (HMMA): y[128px x 64co] = pre . wf^T via split-bf16 mma.sync, then
// out = x + a*y + bb in a light residual pass. Same frag layout as k1 (proven).
// Block 256 thr (8 warps), grid (128 px-tiles, 4 co-groups).
// Dynamic smem: Ah|Al (pre hi/lo, stride 48), Bh|Bl (wf hi/lo), sy[128][72].
// ---------------------------------------------------------------------------
#define K4_AH  0
#define K4_AL  (128*48*2)
#define K4_BH  (2*128*48*2)
#define K4_BL  (2*128*48*2 + 64*48*2)
#define K4_SY  (2*128*48*2 + 2*64*48*2)
#define K4_SMEM (K4_SY + 128*72*4)     // 24576+12288+36864 = 73728 B

__global__ void __launch_bounds__(256) k4_mma(
    const float* __restrict__ x, const float* __restrict__ wf,
    const float* __restrict__ bf, float* __restrict__ out)
{
    extern __shared__ __align__(16) char dsm[];
    __nv_bfloat16* Ah = (__nv_bfloat16*)(dsm + K4_AH);
    __nv_bfloat16* Al = (__nv_bfloat16*)(dsm + K4_AL);
    __nv_bfloat16* Bh = (__nv_bfloat16*)(dsm + K4_BH);
    __nv_bfloat16* Bl = (__nv_bfloat16*)(dsm + K4_BL);
    float*         sy = (float*)(dsm + K4_SY);
    __shared__ float as[64], bbs[64];

    int t = threadIdx.x;
    int w = t >> 5, lane = t & 31;
    int cog = blockIdx.y * 64;
    int p0  = blockIdx.x * 128;

    // stage A: pre tile 128px x 32ch, hi/lo split
    const float4* pre4 = (const float4*)(g_pre + (size_t)p0*32);
#pragma unroll
    for (int i = 0; i < 4; ++i) {
        int idx = i*256 + t;              // 1024 float4
        int px = idx >> 3, c4 = (idx & 7)*4;
        float4 v = pre4[idx];
        float vv[4] = {v.x, v.y, v.z, v.w};
#pragma unroll
        for (int j = 0; j < 4; ++j) {
            __nv_bfloat16 h = __float2bfloat16(vv[j]);
            __nv_bfloat16 l = __float2bfloat16(vv[j] - __bfloat162float(h));
            Ah[px*48 + c4 + j] = h;
            Al[px*48 + c4 + j] = l;
        }
    }
    // stage B: wf rows cog..cog+63 x 32ch, hi/lo
#pragma unroll
    for (int i = 0; i < 8; ++i) {
        int idx = i*256 + t;              // 2048 floats
        int o = idx >> 5, c = idx & 31;
        float v = wf[(size_t)(cog+o)*32 + c];
        __nv_bfloat16 h = __float2bfloat16(v);
        __nv_bfloat16 l = __float2bfloat16(v - __bfloat162float(h));
        Bh[o*48 + c] = h;
        Bl[o*48 + c] = l;
    }
    if (t < 64) {
        float a = g_ab[cog+t];
        as[t]  = a;
        bbs[t] = g_ab[256+cog+t] + a * bf[cog+t];
    }
    __syncthreads();

    // mainloop: warp = 16m x 64n, K=32 (2 k-steps)
    int m0 = w * 16;
    float acc[8][4];
#pragma unroll
    for (int i = 0; i < 8; ++i)
#pragma unroll
        for (int j = 0; j < 4; ++j) acc[i][j] = 0.f;

    int a_row = m0 + (lane & 15);
    int a_col = ((lane >> 4) << 3);
    int b_row = lane & 7;
    int b_col = ((lane >> 3) & 1) << 3;
    uint32_t AhB = smem_u32(Ah), AlB = smem_u32(Al);
    uint32_t BhB = smem_u32(Bh), BlB = smem_u32(Bl);
    uint32_t aOff  = (uint32_t)(a_row*48 + a_col) * 2u;
    uint32_t bOffL = (uint32_t)(b_row*48 + b_col) * 2u;

#pragma unroll
    for (int ks = 0; ks < 2; ++ks) {
        uint32_t kByte = (uint32_t)(ks*16) * 2u;
        uint32_t ah0,ah1,ah2,ah3, al0,al1,al2,al3;
        LDMX4(ah0,ah1,ah2,ah3, AhB + aOff + kByte);
        LDMX4(al0,al1,al2,al3, AlB + aOff + kByte);
#pragma unroll
        for (int nt = 0; nt < 8; ++nt) {
            uint32_t nByte = (uint32_t)((nt*8)*48) * 2u;
            uint32_t bh0,bh1, bl0,bl1;
            LDMX2(bh0,bh1, BhB + bOffL + nByte + kByte);
            LDMX2(bl0,bl1, BlB + bOffL + nByte + kByte);
            MMA16816(acc[nt], ah0,ah1,ah2,ah3, bh0,bh1);
            MMA16816(acc[nt], al0,al1,al2,al3, bh0,bh1);
            MMA16816(acc[nt], ah0,ah1,ah2,ah3, bl0,bl1);
        }
    }

    // frags -> sy[px][co]
    int r  = lane >> 2;
    int c2 = (lane & 3) * 2;
#pragma unroll
    for (int nt = 0; nt < 8; ++nt) {
        int col = nt*8 + c2;
        sy[(m0 + r)*72 + col]     = acc[nt][0];
        sy[(m0 + r)*72 + col + 1] = acc[nt][1];
        sy[(m0 + r + 8)*72 + col]     = acc[nt][2];
        sy[(m0 + r + 8)*72 + col + 1] = acc[nt][3];
    }
    __syncthreads();

    // residual pass: thread = (pixel, co-half of 32)
    int px   = t & 127;
    int half = t >> 7;
    int p = p0 + px;
    int b = p >> 12, hw = p & 4095;
    const float* xrow = x   + (size_t)b*(Cc*HWc) + hw;
    float*       orow = out + (size_t)b*(Cc*HWc) + hw;
    const float* yrow = &sy[px*72 + half*32];
#pragma unroll
    for (int cc = 0; cc < 32; ++cc) {
        int co = half*32 + cc;
        size_t off = (size_t)(cog + co) * HWc;
        orow[off] = xrow[off] + as[co]*yrow[cc] + bbs[co];
    }
}

// ---------------------------------------------------------------------------
extern "C" void kernel_launch(void* const* d_in, const int* in_sizes, int n_in,
                              void* d_out, int out_size)
{
    const float* x      = (const float*)d_in[0];
    const float* vessel = (const float*)d_in[1];
    const float* wk     = (const float*)d_in[2];
    const float* bk     = (const float*)d_in[3];
    const float* wq     = (const float*)d_in[4];
    const float* bq     = (const float*)d_in[5];
    const float* wx     = (const float*)d_in[6];
    const float* bx     = (const float*)d_in[7];
    const float* wf     = (const float*)d_in[8];
    const float* bf     = (const float*)d_in[9];
    const float* gamma  = (const float*)d_in[10];
    const float* beta   = (const float*)d_in[11];
    float* out = (float*)d_out;

    cudaFuncSetAttribute(k4_mma, cudaFuncAttributeMaxDynamicSharedMemorySize, K4_SMEM);

    k1_kqx_mma<<<256, 256>>>(x, vessel, wk, bk, wq, bq, wx, bx);
    k2_attn<<<1024, 128>>>();
    k3_stats<<<64, 256>>>(wf, bf, gamma, beta);
    k4_mma<<<dim3(128,4), 256, K4_SMEM>>>(x, wf, bf, out);
}